// round 9
// baseline (speedup 1.0000x reference)
#include <cuda_runtime.h>
#include <cstdint>
#include <cfloat>
#include <math.h>

#define B_ 8
#define N_ 16384
#define NPOINT_ 1024
#define K_ 32
#define SAMPLE_NUM_ 10
#define SEL_ 7
#define SUBSET_ 29
#define RADIUS_ 0.2f

#define CLUSTER_ 8
#define SLICE_ (N_ / CLUSTER_)        // 2048 points per CTA
#define FPS_CTAS_ (B_ * CLUSTER_)     // 64
#define PPT_ (SLICE_ / 256)           // 8 points per thread

// FPS-selected center coordinates (B, NPOINT, 3)
__device__ float g_centers[B_ * NPOINT_ * 3];
// Packed points: (x, y, z, xx) with xx = ((x*x+y*y)+z*z) reference-rounded
__device__ float4 g_pts[B_ * N_];
// progress[b] = number of centers published for batch b; ready[b] = #CTAs done with g_pts
__device__ unsigned g_progress[B_];
__device__ unsigned g_ready[B_];

struct Perms { unsigned char p[SAMPLE_NUM_][SUBSET_]; };

__device__ __forceinline__ unsigned smem_u32(const void* p) {
    unsigned a;
    asm("{ .reg .u64 t; cvta.to.shared.u64 t, %1; cvt.u32.u64 %0, t; }"
        : "=r"(a) : "l"(p));
    return a;
}
__device__ __forceinline__ unsigned ld_acq(const unsigned* p) {
    unsigned v;
    asm volatile("ld.global.acquire.gpu.u32 %0, [%1];" : "=r"(v) : "l"(p) : "memory");
    return v;
}
__device__ __forceinline__ void st_rel(unsigned* p, unsigned v) {
    asm volatile("st.global.release.gpu.u32 [%0], %1;" :: "l"(p), "r"(v) : "memory");
}

// shared-memory union for the two roles
struct FpsSm {
    float ox[SLICE_], oy[SLICE_], oz[SLICE_];
    unsigned long long warr[8];
    unsigned long long skey[2][CLUSTER_];
    float scx[2][CLUSTER_], scy[2][CLUSTER_], scz[2][CLUSTER_];
};
struct KnnSm {
    unsigned long long cand[256 * 4];
    unsigned long long heads[256];
    unsigned char curs[256];
    int nb[K_];
    float gx[K_], gy[K_], gz[K_];
    float cdx[SAMPLE_NUM_], cdy[SAMPLE_NUM_], cdz[SAMPLE_NUM_];
};

__global__ void init_flags_kernel()
{
    if (threadIdx.x < B_) {
        g_progress[threadIdx.x] = 0u;
        g_ready[threadIdx.x] = 0u;
    }
}

// ======================= Fused kernel: FPS producers + KNN consumers =======================
// bid < 64: cluster-parallel FPS (one 8-CTA cluster per batch), publishing
//           center s via release-store progress[b]=s+1.
// bid >= 64: knn+features for center (s = idx>>3, b = idx&7), acquire-spin
//            on progress[b] >= s+1 (s-major bid order matches production order).
__global__ void __launch_bounds__(256) __cluster_dims__(CLUSTER_, 1, 1)
fused_kernel(const float* __restrict__ xyz, float* __restrict__ out, Perms perms)
{
    __shared__ __align__(16) char smraw[sizeof(FpsSm) > sizeof(KnnSm) ? sizeof(FpsSm) : sizeof(KnnSm)];
    const int bid = blockIdx.x;
    const int t = threadIdx.x;

    if (bid < FPS_CTAS_) {
        // ======================= FPS role =======================
        FpsSm& S = *reinterpret_cast<FpsSm*>(smraw);
        unsigned rank;
        asm("mov.u32 %0, %%cluster_ctarank;" : "=r"(rank));
        const int b = bid >> 3;
        const int base = (int)rank * SLICE_;
        const float* X = xyz + (size_t)b * N_ * 3;

        float px[PPT_], py[PPT_], pz[PPT_], dd[PPT_];
#pragma unroll
        for (int k = 0; k < PPT_; k++) {
            int l = (k << 8) + t;
            int n = base + l;
            float x = X[n * 3 + 0], y = X[n * 3 + 1], z = X[n * 3 + 2];
            px[k] = x; py[k] = y; pz[k] = z;
            S.ox[l] = x; S.oy[l] = y; S.oz[l] = z;
            dd[k] = 1e10f;
            float xx = __fadd_rn(__fadd_rn(__fmul_rn(x, x), __fmul_rn(y, y)),
                                 __fmul_rn(z, z));
            g_pts[(size_t)b * N_ + n] = make_float4(x, y, z, xx);
        }
        __syncthreads();
        if (t == 0) {
            __threadfence();                  // make this CTA's g_pts writes gpu-visible
            atomicAdd(&g_ready[b], 1u);
        }
        // rank0/t0 gates first publish on all 8 CTAs' g_pts being visible
        if (rank == 0 && t == 0) {
            while (ld_acq(&g_ready[b]) < (unsigned)CLUSTER_) { /* fast */ }
        }

        float cx = X[0], cy = X[1], cz = X[2];
        float* outc = g_centers + (size_t)b * NPOINT_ * 3;

        for (int s = 0; s < NPOINT_; s++) {
            if (rank == 0 && t == 0) {
                outc[s * 3 + 0] = cx; outc[s * 3 + 1] = cy; outc[s * 3 + 2] = cz;
                st_rel(&g_progress[b], (unsigned)(s + 1));   // release: orders center stores
            }
            const int par = s & 1;

            // per-thread argmax (strict > keeps first index; n ascending in k)
            float maxd = -1.0f; int bi = 0;
#pragma unroll
            for (int k = 0; k < PPT_; k++) {
                int n = base + (k << 8) + t;
                // match XLA: ((dx*dx + dy*dy) + dz*dz), each op rounded, no FMA
                float dx = __fsub_rn(px[k], cx);
                float dy = __fsub_rn(py[k], cy);
                float dz = __fsub_rn(pz[k], cz);
                float d  = __fadd_rn(__fadd_rn(__fmul_rn(dx, dx), __fmul_rn(dy, dy)),
                                     __fmul_rn(dz, dz));
                float nd = fminf(dd[k], d);
                dd[k] = nd;
                if (nd > maxd) { maxd = nd; bi = n; }
            }
            unsigned hb = __float_as_uint(maxd);
            unsigned mh = __reduce_max_sync(0xffffffffu, hb);
            unsigned cd = (hb == mh) ? ~(unsigned)bi : 0u;
            unsigned ml = __reduce_max_sync(0xffffffffu, cd);
            if ((t & 31) == 0)
                S.warr[t >> 5] = ((unsigned long long)mh << 32) | ml;
            __syncthreads();

            unsigned long long bb = S.warr[0];
#pragma unroll
            for (int w = 1; w < 8; w++) {
                unsigned long long v = S.warr[w];
                bb = (v > bb) ? v : bb;
            }

            if (t < CLUSTER_) {
                int g = (int)(~(unsigned)(bb & 0xffffffffu));
                int l = g - base;
                float wx = S.ox[l], wy = S.oy[l], wz = S.oz[l];
                unsigned a_key = smem_u32(&S.skey[par][rank]);
                unsigned a_cx  = smem_u32(&S.scx[par][rank]);
                unsigned a_cy  = smem_u32(&S.scy[par][rank]);
                unsigned a_cz  = smem_u32(&S.scz[par][rank]);
                unsigned r_key, r_cx, r_cy, r_cz;
                asm("mapa.shared::cluster.u32 %0, %1, %2;" : "=r"(r_key) : "r"(a_key), "r"(t));
                asm("mapa.shared::cluster.u32 %0, %1, %2;" : "=r"(r_cx)  : "r"(a_cx),  "r"(t));
                asm("mapa.shared::cluster.u32 %0, %1, %2;" : "=r"(r_cy)  : "r"(a_cy),  "r"(t));
                asm("mapa.shared::cluster.u32 %0, %1, %2;" : "=r"(r_cz)  : "r"(a_cz),  "r"(t));
                asm volatile("st.shared::cluster.b64 [%0], %1;" :: "r"(r_key), "l"(bb) : "memory");
                asm volatile("st.shared::cluster.b32 [%0], %1;" :: "r"(r_cx), "r"(__float_as_uint(wx)) : "memory");
                asm volatile("st.shared::cluster.b32 [%0], %1;" :: "r"(r_cy), "r"(__float_as_uint(wy)) : "memory");
                asm volatile("st.shared::cluster.b32 [%0], %1;" :: "r"(r_cz), "r"(__float_as_uint(wz)) : "memory");
            }

            asm volatile("barrier.cluster.arrive.aligned;" ::: "memory");
            asm volatile("barrier.cluster.wait.aligned;" ::: "memory");

            unsigned long long w0 = S.skey[par][0];
            int wi = 0;
#pragma unroll
            for (int r = 1; r < CLUSTER_; r++) {
                unsigned long long v = S.skey[par][r];
                if (v > w0) { w0 = v; wi = r; }
            }
            cx = S.scx[par][wi]; cy = S.scy[par][wi]; cz = S.scz[par][wi];
        }
        return;
    }

    // ======================= KNN role =======================
    KnnSm& S = *reinterpret_cast<KnnSm*>(smraw);
    const int idx = bid - FPS_CTAS_;
    const int b = idx & 7;
    const int s = idx >> 3;            // s-major: matches center production order
    const int bs = b * NPOINT_ + s;
    const float4* P = g_pts + (size_t)b * N_;

    if (t == 0) {
        unsigned need = (unsigned)(s + 1);
        while (ld_acq(&g_progress[b]) < need) __nanosleep(256);
    }
    __syncthreads();

    const float cx = g_centers[bs * 3 + 0];
    const float cy = g_centers[bs * 3 + 1];
    const float cz = g_centers[bs * 3 + 2];
    const float cc = __fadd_rn(__fadd_rn(__fmul_rn(cx, cx), __fmul_rn(cy, cy)),
                               __fmul_rn(cz, cz));

    // exact sorted top-4 per thread (strict < keeps first index on ties;
    // n ascending within thread; d2 never -0.0 under RN)
    float v0 = FLT_MAX, v1 = FLT_MAX, v2 = FLT_MAX, v3 = FLT_MAX;
    int i0 = 0, i1 = 0, i2 = 0, i3 = 0;
#pragma unroll 8
    for (int k = 0; k < 64; k++) {
        int n = t + (k << 8);
        float4 p = __ldg(&P[n]);
        float dt = __fadd_rn(__fadd_rn(__fmul_rn(cx, p.x), __fmul_rn(cy, p.y)),
                             __fmul_rn(cz, p.z));
        // match reference: (cc + xx) - 2*dot
        float d2 = __fsub_rn(__fadd_rn(cc, p.w), __fmul_rn(2.0f, dt));
        if (d2 < v3) {
            if (d2 < v2) {
                v3 = v2; i3 = i2;
                if (d2 < v1) {
                    v2 = v1; i2 = i1;
                    if (d2 < v0) { v1 = v0; i1 = i0; v0 = d2; i0 = n; }
                    else         { v1 = d2; i1 = n; }
                } else { v2 = d2; i2 = n; }
            } else { v3 = d2; i3 = n; }
        }
    }
    auto pack = [](float v, int n) -> unsigned long long {
        unsigned fb = __float_as_uint(v);
        fb = (fb & 0x80000000u) ? ~fb : (fb | 0x80000000u);   // monotone map
        return ((unsigned long long)fb << 32) | (unsigned)n;
    };
    S.cand[t * 4 + 0] = pack(v0, i0);
    S.cand[t * 4 + 1] = pack(v1, i1);
    S.cand[t * 4 + 2] = pack(v2, i2);
    S.cand[t * 4 + 3] = pack(v3, i3);
    S.heads[t] = S.cand[t * 4 + 0];
    S.curs[t] = 0;
    __syncthreads();

    // ---- warp 0: 32-round 256-way merge (ascending d2, ties -> lower index) ----
    if (t < 32) {
        const int baseT = t * 8;
        for (int j = 0; j < K_; j++) {
            unsigned long long lm = S.heads[baseT]; int li = 0;
#pragma unroll
            for (int i = 1; i < 8; i++) {
                unsigned long long v = S.heads[baseT + i];
                if (v < lm) { lm = v; li = i; }
            }
            unsigned hi = (unsigned)(lm >> 32), lo = (unsigned)lm;
            unsigned mh = __reduce_min_sync(0xffffffffu, hi);
            unsigned cl = (hi == mh) ? lo : 0xffffffffu;
            unsigned ml = __reduce_min_sync(0xffffffffu, cl);
            unsigned long long w = ((unsigned long long)mh << 32) | ml;
            if (t == 0) S.nb[j] = (int)ml;
            if (lm == w) {                       // unique owner lane
                int T = baseT + li;
                int c = (int)S.curs[T] + 1;
                S.curs[T] = (unsigned char)c;
                unsigned long long nh;
                if (c < 4) {
                    nh = S.cand[T * 4 + c];
                } else {
                    // exact refill: min key > w over T's 64 points (rare)
                    nh = 0xFFFFFFFFFFFFFFFFull;
                    for (int k = 0; k < 64; k++) {
                        int n = T + (k << 8);
                        float4 p = __ldg(&P[n]);
                        float dt = __fadd_rn(__fadd_rn(__fmul_rn(cx, p.x), __fmul_rn(cy, p.y)),
                                             __fmul_rn(cz, p.z));
                        float d2 = __fsub_rn(__fadd_rn(cc, p.w), __fmul_rn(2.0f, dt));
                        unsigned fb = __float_as_uint(d2);
                        fb = (fb & 0x80000000u) ? ~fb : (fb | 0x80000000u);
                        unsigned long long pk = ((unsigned long long)fb << 32) | (unsigned)n;
                        if (pk > w && pk < nh) nh = pk;
                    }
                }
                S.heads[T] = nh;
            }
        }
    }
    __syncthreads();

    // ---- gather the 32 neighbors (in selection order) ----
    if (t < K_) {
        int n = S.nb[t];
        float4 p = P[n];
        S.gx[t] = p.x; S.gy[t] = p.y; S.gz[t] = p.z;
    }
    __syncthreads();

    // ---- 10 candidate centroids: mean over fixed 29-element permutation subsets ----
    if (t < SAMPLE_NUM_) {
        float ax = 0.f, ay = 0.f, az = 0.f;
        for (int j = 0; j < SUBSET_; j++) {
            int p = perms.p[t][j];
            ax += S.gx[p]; ay += S.gy[p]; az += S.gz[p];
        }
        S.cdx[t] = ax / (float)SUBSET_;
        S.cdy[t] = ay / (float)SUBSET_;
        S.cdz[t] = az / (float)SUBSET_;
    }
    __syncthreads();

    // ---- candidate selection (7 most central of 10) + features ----
    if (t == 0) {
        float sq[SAMPLE_NUM_], ps[SAMPLE_NUM_];
        for (int j = 0; j < SAMPLE_NUM_; j++)
            sq[j] = S.cdx[j] * S.cdx[j] + S.cdy[j] * S.cdy[j] + S.cdz[j] * S.cdz[j];
        for (int j = 0; j < SAMPLE_NUM_; j++) {
            float acc = 0.f;
            for (int k2 = 0; k2 < SAMPLE_NUM_; k2++) {
                float dt = S.cdx[j] * S.cdx[k2] + S.cdy[j] * S.cdy[k2] + S.cdz[j] * S.cdz[k2];
                acc += sq[j] + sq[k2] - 2.0f * dt;
            }
            ps[j] = acc;
        }
        bool used[SAMPLE_NUM_];
        for (int j = 0; j < SAMPLE_NUM_; j++) used[j] = false;
        float mx = 0.f, my = 0.f, mz = 0.f;
        for (int r = 0; r < SEL_; r++) {
            int bsel = 0; float bv = FLT_MAX;
            for (int k2 = 0; k2 < SAMPLE_NUM_; k2++)
                if (!used[k2] && ps[k2] < bv) { bv = ps[k2]; bsel = k2; }
            used[bsel] = true;
            mx += S.cdx[bsel]; my += S.cdy[bsel]; mz += S.cdz[bsel];
        }
        mx /= (float)SEL_; my /= (float)SEL_; mz /= (float)SEL_;

        float ref_norm = sqrtf(cx * cx + cy * cy + cz * cz);
        float den = ref_norm + 1e-4f;
        float ux = cx / den, uy = cy / den, uz = cz / den;
        float ix = RADIUS_ * ux + cx, iy = RADIUS_ * uy + cy, iz = RADIUS_ * uz + cz;

        float crx = cx - mx, cry = cy - my, crz = cz - mz;
        float crd = sqrtf(crx * crx + cry * cry + crz * crz);
        float cvx = ix - mx, cvy = iy - my, cvz = iz - mz;
        float cid = sqrtf(cvx * cvx + cvy * cvy + cvz * cvz);
        float dot = crx * cvx + cry * cvy + crz * cvz;
        float ang_rci = dot / (crd * cid + 1e-6f);

        float irx = cx - ix, iry = cy - iy, irz = cz - iz;
        float icx = mx - ix, icy = my - iy, icz = mz - iz;
        float dot2 = irx * icx + iry * icy + irz * icz;
        float ang_ric = dot2 / (RADIUS_ * cid + 1e-6f);

        float* o = out + (size_t)bs * 5;
        o[0] = ref_norm; o[1] = crd; o[2] = cid; o[3] = ang_rci; o[4] = ang_ric;
    }
}

// ======================= Host: threefry-2x32 (JAX partitionable PRNG) =======================
static inline uint32_t rotl32_(uint32_t x, int r) { return (x << r) | (x >> (32 - r)); }

static void tf2x32_(uint32_t k0, uint32_t k1, uint32_t x0, uint32_t x1,
                    uint32_t& o0, uint32_t& o1)
{
    static const int R0[4] = {13, 15, 26, 6};
    static const int R1[4] = {17, 29, 16, 24};
    uint32_t ks[3] = {k0, k1, k0 ^ k1 ^ 0x1BD11BDAu};
    x0 += ks[0]; x1 += ks[1];
    for (int i = 0; i < 5; i++) {
        const int* R = (i & 1) ? R1 : R0;
        for (int j = 0; j < 4; j++) { x0 += x1; x1 = rotl32_(x1, R[j]); x1 ^= x0; }
        x0 += ks[(i + 1) % 3];
        x1 += ks[(i + 2) % 3] + (uint32_t)(i + 1);
    }
    o0 = x0; o1 = x1;
}

// jax.random.permutation(fold_in(key(42), i), 32)[:29], threefry partitionable mode.
static void make_perms(unsigned char p[SAMPLE_NUM_][SUBSET_])
{
    for (int i = 0; i < SAMPLE_NUM_; i++) {
        uint32_t k0, k1, s0, s1;
        tf2x32_(0u, 42u, 0u, (uint32_t)i, k0, k1);     // fold_in
        tf2x32_(k0, k1, 0u, 1u, s0, s1);               // split -> subkey (index 1)
        uint32_t bits[K_];
        for (int j = 0; j < K_; j++) {
            uint32_t hi, lo;
            tf2x32_(s0, s1, 0u, (uint32_t)j, hi, lo);
            bits[j] = hi ^ lo;                         // 32-bit path XORs both words
        }
        int idx[K_];
        for (int j = 0; j < K_; j++) idx[j] = j;
        for (int a = 1; a < K_; a++) {                 // stable insertion sort
            uint32_t bv = bits[a]; int iv = idx[a]; int c = a - 1;
            while (c >= 0 && bits[c] > bv) {
                bits[c + 1] = bits[c]; idx[c + 1] = idx[c]; c--;
            }
            bits[c + 1] = bv; idx[c + 1] = iv;
        }
        for (int j = 0; j < SUBSET_; j++) p[i][j] = (unsigned char)idx[j];
    }
}

extern "C" void kernel_launch(void* const* d_in, const int* in_sizes, int n_in,
                              void* d_out, int out_size)
{
    (void)in_sizes; (void)n_in; (void)out_size;
    const float* xyz = (const float*)d_in[0];
    float* out = (float*)d_out;

    Perms perms;
    make_perms(perms.p);   // deterministic, cheap, every call

    init_flags_kernel<<<1, 32>>>();
    fused_kernel<<<FPS_CTAS_ + B_ * NPOINT_, 256>>>(xyz, out, perms);
}

// round 10
// speedup vs baseline: 1.4784x; 1.4784x over previous
#include <cuda_runtime.h>
#include <cstdint>
#include <cfloat>
#include <math.h>

#define B_ 8
#define N_ 16384
#define NPOINT_ 1024
#define K_ 32
#define SAMPLE_NUM_ 10
#define SEL_ 7
#define SUBSET_ 29
#define RADIUS_ 0.2f

#define CLUSTER_ 8
#define SLICE_ (N_ / CLUSTER_)        // 2048 points per CTA
#define FPS_T_ 256
#define PPT_ (SLICE_ / FPS_T_)        // 8 points per thread

#define CTILE_ 4                      // centers per knn CTA
#define KNN_TILES_ (NPOINT_ / CTILE_) // 256 tiles per batch

// FPS-selected center coordinates (B, NPOINT, 3)
__device__ float g_centers[B_ * NPOINT_ * 3];
// Packed points: (x, y, z, xx) with xx = ((x*x+y*y)+z*z) reference-rounded
__device__ float4 g_pts[B_ * N_];

struct Perms { unsigned char p[SAMPLE_NUM_][SUBSET_]; };

__device__ __forceinline__ unsigned smem_u32(const void* p) {
    unsigned a;
    asm("{ .reg .u64 t; cvta.to.shared.u64 t, %1; cvt.u32.u64 %0, t; }"
        : "=r"(a) : "l"(p));
    return a;
}

// ======================= Kernel A: cluster-parallel FPS (proven R7 version) ===============
__global__ __launch_bounds__(FPS_T_) __cluster_dims__(CLUSTER_, 1, 1)
void fps_cluster_kernel(const float* __restrict__ xyz)
{
    __shared__ float ox[SLICE_], oy[SLICE_], oz[SLICE_];
    __shared__ unsigned long long warr[FPS_T_ / 32];
    __shared__ unsigned long long skey[2][CLUSTER_];
    __shared__ float scx[2][CLUSTER_], scy[2][CLUSTER_], scz[2][CLUSTER_];

    const int t = threadIdx.x;
    unsigned rank;
    asm("mov.u32 %0, %%cluster_ctarank;" : "=r"(rank));
    const int b = blockIdx.x >> 3;
    const int base = (int)rank * SLICE_;
    const float* X = xyz + (size_t)b * N_ * 3;

    float px[PPT_], py[PPT_], pz[PPT_], dd[PPT_];
#pragma unroll
    for (int k = 0; k < PPT_; k++) {
        int l = (k << 8) + t;
        int n = base + l;
        float x = X[n * 3 + 0], y = X[n * 3 + 1], z = X[n * 3 + 2];
        px[k] = x; py[k] = y; pz[k] = z;
        ox[l] = x; oy[l] = y; oz[l] = z;
        dd[k] = 1e10f;
        float xx = __fadd_rn(__fadd_rn(__fmul_rn(x, x), __fmul_rn(y, y)),
                             __fmul_rn(z, z));
        g_pts[(size_t)b * N_ + n] = make_float4(x, y, z, xx);
    }
    __syncthreads();

    float cx = X[0], cy = X[1], cz = X[2];
    float* outc = g_centers + (size_t)b * NPOINT_ * 3;

    for (int s = 0; s < NPOINT_; s++) {
        if (rank == 0 && t == 0) {
            outc[s * 3 + 0] = cx; outc[s * 3 + 1] = cy; outc[s * 3 + 2] = cz;
        }
        const int par = s & 1;

        // per-thread argmax (strict > keeps first index; n ascending in k)
        float maxd = -1.0f; int bi = 0;
#pragma unroll
        for (int k = 0; k < PPT_; k++) {
            int n = base + (k << 8) + t;
            // match XLA: ((dx*dx + dy*dy) + dz*dz), each op rounded, no FMA
            float dx = __fsub_rn(px[k], cx);
            float dy = __fsub_rn(py[k], cy);
            float dz = __fsub_rn(pz[k], cz);
            float d  = __fadd_rn(__fadd_rn(__fmul_rn(dx, dx), __fmul_rn(dy, dy)),
                                 __fmul_rn(dz, dz));
            float nd = fminf(dd[k], d);
            dd[k] = nd;
            if (nd > maxd) { maxd = nd; bi = n; }
        }
        unsigned hb = __float_as_uint(maxd);
        unsigned mh = __reduce_max_sync(0xffffffffu, hb);
        unsigned cd = (hb == mh) ? ~(unsigned)bi : 0u;
        unsigned ml = __reduce_max_sync(0xffffffffu, cd);
        if ((t & 31) == 0)
            warr[t >> 5] = ((unsigned long long)mh << 32) | ml;
        __syncthreads();

        unsigned long long bb = warr[0];
#pragma unroll
        for (int w = 1; w < FPS_T_ / 32; w++) {
            unsigned long long v = warr[w];
            bb = (v > bb) ? v : bb;
        }

        if (t < CLUSTER_) {
            int g = (int)(~(unsigned)(bb & 0xffffffffu));
            int l = g - base;
            float wx = ox[l], wy = oy[l], wz = oz[l];
            unsigned a_key = smem_u32(&skey[par][rank]);
            unsigned a_cx  = smem_u32(&scx[par][rank]);
            unsigned a_cy  = smem_u32(&scy[par][rank]);
            unsigned a_cz  = smem_u32(&scz[par][rank]);
            unsigned r_key, r_cx, r_cy, r_cz;
            asm("mapa.shared::cluster.u32 %0, %1, %2;" : "=r"(r_key) : "r"(a_key), "r"(t));
            asm("mapa.shared::cluster.u32 %0, %1, %2;" : "=r"(r_cx)  : "r"(a_cx),  "r"(t));
            asm("mapa.shared::cluster.u32 %0, %1, %2;" : "=r"(r_cy)  : "r"(a_cy),  "r"(t));
            asm("mapa.shared::cluster.u32 %0, %1, %2;" : "=r"(r_cz)  : "r"(a_cz),  "r"(t));
            asm volatile("st.shared::cluster.b64 [%0], %1;" :: "r"(r_key), "l"(bb) : "memory");
            asm volatile("st.shared::cluster.b32 [%0], %1;" :: "r"(r_cx), "r"(__float_as_uint(wx)) : "memory");
            asm volatile("st.shared::cluster.b32 [%0], %1;" :: "r"(r_cy), "r"(__float_as_uint(wy)) : "memory");
            asm volatile("st.shared::cluster.b32 [%0], %1;" :: "r"(r_cz), "r"(__float_as_uint(wz)) : "memory");
        }

        asm volatile("barrier.cluster.arrive.aligned;" ::: "memory");
        asm volatile("barrier.cluster.wait.aligned;" ::: "memory");

        unsigned long long w0 = skey[par][0];
        int wi = 0;
#pragma unroll
        for (int r = 1; r < CLUSTER_; r++) {
            unsigned long long v = skey[par][r];
            if (v > w0) { w0 = v; wi = r; }
        }
        cx = scx[par][wi]; cy = scy[par][wi]; cz = scz[par][wi];
    }
}

// ======================= Kernel B: tiled KNN + robust centroid + features ==================
// One CTA per 4 centers (same batch): each point loaded ONCE and scored against
// 4 centers (register top-4 per center). Warps 0-3 then run 4 concurrent
// 256-way merges (transposed heads -> no bank conflicts) + per-warp features.
__global__ __launch_bounds__(256, 4) void knn_feat_kernel(float* __restrict__ out,
                                                          Perms perms)
{
    __shared__ unsigned long long cand[CTILE_][256][4];   // 32KB
    __shared__ unsigned long long heads[CTILE_][256];     // 8KB, [(T&7)*32 + (T>>3)]
    __shared__ unsigned char curs[CTILE_][256];           // 1KB
    __shared__ int nb[CTILE_][K_];
    __shared__ float gx[CTILE_][K_], gy[CTILE_][K_], gz[CTILE_][K_];
    __shared__ float cdv[CTILE_][SAMPLE_NUM_][3];

    const int bid = blockIdx.x;
    const int b = bid / KNN_TILES_;
    const int tile = bid % KNN_TILES_;
    const int s0 = tile * CTILE_;
    const int t = threadIdx.x;
    const float4* P = g_pts + (size_t)b * N_;

    float ccx[CTILE_], ccy[CTILE_], ccz[CTILE_], ccc[CTILE_];
#pragma unroll
    for (int c = 0; c < CTILE_; c++) {
        int bs = b * NPOINT_ + s0 + c;
        float x = g_centers[bs * 3 + 0];
        float y = g_centers[bs * 3 + 1];
        float z = g_centers[bs * 3 + 2];
        ccx[c] = x; ccy[c] = y; ccz[c] = z;
        ccc[c] = __fadd_rn(__fadd_rn(__fmul_rn(x, x), __fmul_rn(y, y)),
                           __fmul_rn(z, z));
    }

    // scan: each point loaded once, scored vs 4 centers; exact sorted top-4
    // per center (strict < keeps first index; n ascending; d2 never -0.0)
    float v0[CTILE_], v1[CTILE_], v2[CTILE_], v3[CTILE_];
    int i0[CTILE_], i1[CTILE_], i2[CTILE_], i3[CTILE_];
#pragma unroll
    for (int c = 0; c < CTILE_; c++) {
        v0[c] = v1[c] = v2[c] = v3[c] = FLT_MAX;
        i0[c] = i1[c] = i2[c] = i3[c] = 0;
    }
#pragma unroll 4
    for (int k = 0; k < 64; k++) {
        int n = t + (k << 8);
        float4 p = __ldg(&P[n]);
#pragma unroll
        for (int c = 0; c < CTILE_; c++) {
            float dt = __fadd_rn(__fadd_rn(__fmul_rn(ccx[c], p.x), __fmul_rn(ccy[c], p.y)),
                                 __fmul_rn(ccz[c], p.z));
            // match reference: (cc + xx) - 2*dot
            float d2 = __fsub_rn(__fadd_rn(ccc[c], p.w), __fmul_rn(2.0f, dt));
            if (d2 < v3[c]) {
                if (d2 < v2[c]) {
                    v3[c] = v2[c]; i3[c] = i2[c];
                    if (d2 < v1[c]) {
                        v2[c] = v1[c]; i2[c] = i1[c];
                        if (d2 < v0[c]) { v1[c] = v0[c]; i1[c] = i0[c]; v0[c] = d2; i0[c] = n; }
                        else             { v1[c] = d2; i1[c] = n; }
                    } else { v2[c] = d2; i2[c] = n; }
                } else { v3[c] = d2; i3[c] = n; }
            }
        }
    }
    auto pack = [](float v, int n) -> unsigned long long {
        unsigned fb = __float_as_uint(v);
        fb = (fb & 0x80000000u) ? ~fb : (fb | 0x80000000u);   // monotone map
        return ((unsigned long long)fb << 32) | (unsigned)n;
    };
    const int hslot = (t & 7) * 32 + (t >> 3);   // transposed heads slot
#pragma unroll
    for (int c = 0; c < CTILE_; c++) {
        unsigned long long k0 = pack(v0[c], i0[c]);
        cand[c][t][0] = k0;
        cand[c][t][1] = pack(v1[c], i1[c]);
        cand[c][t][2] = pack(v2[c], i2[c]);
        cand[c][t][3] = pack(v3[c], i3[c]);
        heads[c][hslot] = k0;
        curs[c][t] = 0;
    }
    __syncthreads();

    // ---- warps 0..3: concurrent 256-way merges (ascending d2, ties -> lower idx) ----
    const int wid = t >> 5;
    const int lane = t & 31;
    if (wid < CTILE_) {
        const int c = wid;
        for (int j = 0; j < K_; j++) {
            // lane scans its 8 heads: heads[c][i*32 + lane], 2-way conflict only
            unsigned long long lm = heads[c][lane]; int li = 0;
#pragma unroll
            for (int i = 1; i < 8; i++) {
                unsigned long long v = heads[c][i * 32 + lane];
                if (v < lm) { lm = v; li = i; }
            }
            unsigned hi = (unsigned)(lm >> 32), lo = (unsigned)lm;
            unsigned mh = __reduce_min_sync(0xffffffffu, hi);
            unsigned cl = (hi == mh) ? lo : 0xffffffffu;
            unsigned ml = __reduce_min_sync(0xffffffffu, cl);
            unsigned long long w = ((unsigned long long)mh << 32) | ml;
            if (lane == 0) nb[c][j] = (int)ml;
            if (lm == w) {                       // unique owner lane
                int T = lane * 8 + li;
                int cur = (int)curs[c][T] + 1;
                curs[c][T] = (unsigned char)cur;
                unsigned long long nh;
                if (cur < 4) {
                    nh = cand[c][T][cur];
                } else {
                    // exact refill: min key > w over T's 64 points (rare)
                    nh = 0xFFFFFFFFFFFFFFFFull;
                    for (int k = 0; k < 64; k++) {
                        int n = T + (k << 8);
                        float4 p = __ldg(&P[n]);
                        float dt = __fadd_rn(__fadd_rn(__fmul_rn(ccx[c], p.x), __fmul_rn(ccy[c], p.y)),
                                             __fmul_rn(ccz[c], p.z));
                        float d2 = __fsub_rn(__fadd_rn(ccc[c], p.w), __fmul_rn(2.0f, dt));
                        unsigned fb = __float_as_uint(d2);
                        fb = (fb & 0x80000000u) ? ~fb : (fb | 0x80000000u);
                        unsigned long long pk = ((unsigned long long)fb << 32) | (unsigned)n;
                        if (pk > w && pk < nh) nh = pk;
                    }
                }
                heads[c][li * 32 + lane] = nh;
            }
        }
        __syncwarp();

        // ---- gather the 32 neighbors (selection order) ----
        {
            int n = nb[c][lane];
            float4 p = __ldg(&P[n]);
            gx[c][lane] = p.x; gy[c][lane] = p.y; gz[c][lane] = p.z;
        }
        __syncwarp();

        // ---- 10 candidate centroids (lanes 0..9) ----
        if (lane < SAMPLE_NUM_) {
            float ax = 0.f, ay = 0.f, az = 0.f;
            for (int j = 0; j < SUBSET_; j++) {
                int p = perms.p[lane][j];
                ax += gx[c][p]; ay += gy[c][p]; az += gz[c][p];
            }
            cdv[c][lane][0] = ax / (float)SUBSET_;
            cdv[c][lane][1] = ay / (float)SUBSET_;
            cdv[c][lane][2] = az / (float)SUBSET_;
        }
        __syncwarp();

        // ---- candidate selection (7 most central of 10) + features (lane 0) ----
        if (lane == 0) {
            float sq[SAMPLE_NUM_], ps[SAMPLE_NUM_];
            for (int j = 0; j < SAMPLE_NUM_; j++)
                sq[j] = cdv[c][j][0] * cdv[c][j][0] + cdv[c][j][1] * cdv[c][j][1]
                      + cdv[c][j][2] * cdv[c][j][2];
            for (int j = 0; j < SAMPLE_NUM_; j++) {
                float acc = 0.f;
                for (int k2 = 0; k2 < SAMPLE_NUM_; k2++) {
                    float dt = cdv[c][j][0] * cdv[c][k2][0] + cdv[c][j][1] * cdv[c][k2][1]
                             + cdv[c][j][2] * cdv[c][k2][2];
                    acc += sq[j] + sq[k2] - 2.0f * dt;
                }
                ps[j] = acc;
            }
            bool used[SAMPLE_NUM_];
            for (int j = 0; j < SAMPLE_NUM_; j++) used[j] = false;
            float mx = 0.f, my = 0.f, mz = 0.f;
            for (int r = 0; r < SEL_; r++) {
                int bsel = 0; float bv = FLT_MAX;
                for (int k2 = 0; k2 < SAMPLE_NUM_; k2++)
                    if (!used[k2] && ps[k2] < bv) { bv = ps[k2]; bsel = k2; }
                used[bsel] = true;
                mx += cdv[c][bsel][0]; my += cdv[c][bsel][1]; mz += cdv[c][bsel][2];
            }
            mx /= (float)SEL_; my /= (float)SEL_; mz /= (float)SEL_;

            float cx = ccx[c], cy = ccy[c], cz = ccz[c];
            float ref_norm = sqrtf(cx * cx + cy * cy + cz * cz);
            float den = ref_norm + 1e-4f;
            float ux = cx / den, uy = cy / den, uz = cz / den;
            float ix = RADIUS_ * ux + cx, iy = RADIUS_ * uy + cy, iz = RADIUS_ * uz + cz;

            float crx = cx - mx, cry = cy - my, crz = cz - mz;
            float crd = sqrtf(crx * crx + cry * cry + crz * crz);
            float cvx = ix - mx, cvy = iy - my, cvz = iz - mz;
            float cid = sqrtf(cvx * cvx + cvy * cvy + cvz * cvz);
            float dot = crx * cvx + cry * cvy + crz * cvz;
            float ang_rci = dot / (crd * cid + 1e-6f);

            float irx = cx - ix, iry = cy - iy, irz = cz - iz;
            float icx = mx - ix, icy = my - iy, icz = mz - iz;
            float dot2 = irx * icx + iry * icy + irz * icz;
            float ang_ric = dot2 / (RADIUS_ * cid + 1e-6f);

            int bs = b * NPOINT_ + s0 + c;
            float* o = out + (size_t)bs * 5;
            o[0] = ref_norm; o[1] = crd; o[2] = cid; o[3] = ang_rci; o[4] = ang_ric;
        }
    }
}

// ======================= Host: threefry-2x32 (JAX partitionable PRNG) =======================
static inline uint32_t rotl32_(uint32_t x, int r) { return (x << r) | (x >> (32 - r)); }

static void tf2x32_(uint32_t k0, uint32_t k1, uint32_t x0, uint32_t x1,
                    uint32_t& o0, uint32_t& o1)
{
    static const int R0[4] = {13, 15, 26, 6};
    static const int R1[4] = {17, 29, 16, 24};
    uint32_t ks[3] = {k0, k1, k0 ^ k1 ^ 0x1BD11BDAu};
    x0 += ks[0]; x1 += ks[1];
    for (int i = 0; i < 5; i++) {
        const int* R = (i & 1) ? R1 : R0;
        for (int j = 0; j < 4; j++) { x0 += x1; x1 = rotl32_(x1, R[j]); x1 ^= x0; }
        x0 += ks[(i + 1) % 3];
        x1 += ks[(i + 2) % 3] + (uint32_t)(i + 1);
    }
    o0 = x0; o1 = x1;
}

// jax.random.permutation(fold_in(key(42), i), 32)[:29], threefry partitionable mode.
static void make_perms(unsigned char p[SAMPLE_NUM_][SUBSET_])
{
    for (int i = 0; i < SAMPLE_NUM_; i++) {
        uint32_t k0, k1, s0, s1;
        tf2x32_(0u, 42u, 0u, (uint32_t)i, k0, k1);     // fold_in
        tf2x32_(k0, k1, 0u, 1u, s0, s1);               // split -> subkey (index 1)
        uint32_t bits[K_];
        for (int j = 0; j < K_; j++) {
            uint32_t hi, lo;
            tf2x32_(s0, s1, 0u, (uint32_t)j, hi, lo);
            bits[j] = hi ^ lo;                         // 32-bit path XORs both words
        }
        int idx[K_];
        for (int j = 0; j < K_; j++) idx[j] = j;
        for (int a = 1; a < K_; a++) {                 // stable insertion sort
            uint32_t bv = bits[a]; int iv = idx[a]; int c = a - 1;
            while (c >= 0 && bits[c] > bv) {
                bits[c + 1] = bits[c]; idx[c + 1] = idx[c]; c--;
            }
            bits[c + 1] = bv; idx[c + 1] = iv;
        }
        for (int j = 0; j < SUBSET_; j++) p[i][j] = (unsigned char)idx[j];
    }
}

extern "C" void kernel_launch(void* const* d_in, const int* in_sizes, int n_in,
                              void* d_out, int out_size)
{
    (void)in_sizes; (void)n_in; (void)out_size;
    const float* xyz = (const float*)d_in[0];
    float* out = (float*)d_out;

    Perms perms;
    make_perms(perms.p);   // deterministic, cheap, every call

    fps_cluster_kernel<<<B_ * CLUSTER_, FPS_T_>>>(xyz);
    knn_feat_kernel<<<B_ * KNN_TILES_, 256>>>(out, perms);
}